// round 1
// baseline (speedup 1.0000x reference)
#include <cuda_runtime.h>
#include <math.h>

#define BB 16
#define NN 2048
#define DIN 160
#define NCTX 2047
#define NCH 8
#define CHUNK 256

// scratch (no allocations allowed)
__device__ float g_part[NCH * BB * 96 * 32];  // per-chunk partial correlations
__device__ float g_W[BB * 96 * 64];           // per-batch combined logits weight [V(32x64); Emb(64x64)]

// ---------------------------------------------------------------------------
// Kernel 1: per (chunk,batch) partial of  res[r][j] = sum_{n in chunk, n<2047} x[b,r,n]*x[b,j,n]
//           r in [0,96), j in [0,32).  rows 0:32 -> P, rows 32:96 -> U.
// ---------------------------------------------------------------------------
__global__ void k1_corr(const float* __restrict__ x) {
    int b = blockIdx.y, ch = blockIdx.x, tid = threadIdx.x;
    __shared__ float sh[96 * 33];
    float acc[12];
#pragma unroll
    for (int k = 0; k < 12; k++) acc[k] = 0.f;

    int cg = tid & 15;   // col group: cols 2*cg, 2*cg+1
    int rg = tid >> 4;   // row group: rows 6*rg .. 6*rg+5
    const float* xb = x + (size_t)b * DIN * NN;
    int n0 = ch * CHUNK;

    for (int t = 0; t < CHUNK; t += 32) {
        // cooperative load of tile [96 rows][32 cols]
#pragma unroll
        for (int k = 0; k < 12; k++) {
            int idx = tid + k * 256;
            int r = idx >> 5, c = idx & 31;
            int n = n0 + t + c;
            sh[r * 33 + c] = (n < NCTX) ? xb[r * NN + n] : 0.f;
        }
        __syncthreads();
#pragma unroll 8
        for (int nn = 0; nn < 32; nn++) {
            float q0 = sh[(2 * cg) * 33 + nn];
            float q1 = sh[(2 * cg + 1) * 33 + nn];
#pragma unroll
            for (int k = 0; k < 6; k++) {
                float v = sh[(6 * rg + k) * 33 + nn];
                acc[2 * k]     += v * q0;
                acc[2 * k + 1] += v * q1;
            }
        }
        __syncthreads();
    }
    float* out = g_part + ((size_t)(ch * BB + b) * 96) * 32;
#pragma unroll
    for (int k = 0; k < 6; k++) {
        out[(6 * rg + k) * 32 + 2 * cg]     = acc[2 * k];
        out[(6 * rg + k) * 32 + 2 * cg + 1] = acc[2 * k + 1];
    }
}

// ---------------------------------------------------------------------------
// Kernel 2: per-batch small algebra (one block per batch).
//   P(32x32), U(64x32) from partials; S0 = Emb*U;
//   loop l: R += c*diag(a_l)*S ; Tmp = c*diag(a_l)*S*P ; S += M*Tmp
//   V = R^T * Emb (32x64); g_W[b] = [V ; Emb]
// ---------------------------------------------------------------------------
__global__ void k2_solve(const float* __restrict__ alpha,
                         const float* __restrict__ kparam,
                         const float* __restrict__ emb,
                         const float* __restrict__ Mm) {
    int b = blockIdx.x, tid = threadIdx.x;
    __shared__ float smem[11264];
    float* sEM = smem;           // 4096: Emb, later M, later Emb again
    float* sP  = smem + 4096;    // 1024
    float* sS  = smem + 5120;    // 2048
    float* sT  = smem + 7168;    // 2048: U, later Tmp
    float* sR  = smem + 9216;    // 2048

    float cfac = kparam[0] / (float)NCTX;

    // reduce partials: P
    for (int e = tid; e < 1024; e += 256) {
        float s = 0.f;
        for (int ch = 0; ch < NCH; ch++)
            s += g_part[((size_t)(ch * BB + b) * 96) * 32 + e];
        sP[e] = s;
    }
    // reduce partials: U (rows 32..95)
    for (int e = tid; e < 2048; e += 256) {
        float s = 0.f;
        for (int ch = 0; ch < NCH; ch++)
            s += g_part[((size_t)(ch * BB + b) * 96 + 32) * 32 + e];
        sT[e] = s;
    }
    for (int e = tid; e < 4096; e += 256) sEM[e] = emb[e];
    __syncthreads();

    // S0 = Emb * U   (64x64 * 64x32)
#pragma unroll
    for (int k = 0; k < 8; k++) {
        int e = tid + k * 256;
        int i = e >> 5, j = e & 31;
        float s = 0.f;
#pragma unroll 8
        for (int c = 0; c < 64; c++) s += sEM[i * 64 + c] * sT[c * 32 + j];
        sS[e] = s;
    }
    __syncthreads();

    // M into sEM, zero R
    for (int e = tid; e < 4096; e += 256) sEM[e] = Mm[e];
    for (int e = tid; e < 2048; e += 256) sR[e] = 0.f;
    __syncthreads();

    for (int l = 0; l < 3; l++) {
        // phase A: R += c*a_i*S ; Tmp = c*a_i * (S*P)
#pragma unroll
        for (int k = 0; k < 8; k++) {
            int e = tid + k * 256;
            int i = e >> 5, j = e & 31;
            float a = cfac * alpha[l * 64 + i];
            sR[e] += a * sS[e];
            float t = 0.f;
#pragma unroll 8
            for (int jj = 0; jj < 32; jj++) t += sS[i * 32 + jj] * sP[jj * 32 + j];
            sT[e] = a * t;
        }
        __syncthreads();
        // phase B: S += M * Tmp
#pragma unroll
        for (int k = 0; k < 8; k++) {
            int e = tid + k * 256;
            int r = e >> 5, j = e & 31;
            float t = 0.f;
#pragma unroll 8
            for (int i = 0; i < 64; i++) t += sEM[r * 64 + i] * sT[i * 32 + j];
            sS[e] += t;
        }
        __syncthreads();
    }

    // reload Emb
    for (int e = tid; e < 4096; e += 256) sEM[e] = emb[e];
    __syncthreads();

    // V[j][c] = sum_i R[i][j] * Emb[i][c]   (rows 0:32 of g_W[b])
#pragma unroll
    for (int k = 0; k < 8; k++) {
        int e = tid + k * 256;
        int j = e >> 6, c = e & 63;
        float v = 0.f;
#pragma unroll 8
        for (int i = 0; i < 64; i++) v += sR[i * 32 + j] * sEM[i * 64 + c];
        g_W[(size_t)(b * 96 + j) * 64 + c] = v;
    }
    // rows 32:96 of g_W[b] = Emb
    for (int e = tid; e < 4096; e += 256)
        g_W[(size_t)b * 96 * 64 + 32 * 64 + e] = sEM[e];
}

// ---------------------------------------------------------------------------
// Kernel 3: logits + softmax.
//   logits[b,n,c] = sum_{d<32} x[b,d,n]*W[d][c] + sum_{d<64} x[b,96+d,n]*W[32+d][c]
// ---------------------------------------------------------------------------
__global__ void __launch_bounds__(128) k3_out(const float* __restrict__ x,
                                              float* __restrict__ out,
                                              int write_pred) {
    int b = blockIdx.y;
    int n = blockIdx.x * 128 + threadIdx.x;
    __shared__ float sW[96 * 64];
    for (int e = threadIdx.x; e < 6144; e += 128)
        sW[e] = g_W[(size_t)b * 6144 + e];
    __syncthreads();

    const float* xb = x + (size_t)b * DIN * NN;
    const float4* sW4 = (const float4*)sW;

    float acc[64];
#pragma unroll
    for (int c = 0; c < 64; c++) acc[c] = 0.f;

#pragma unroll 8
    for (int d = 0; d < 96; d++) {
        int row = d + ((d >= 32) ? 64 : 0);   // x rows 0:32 then 96:160
        float xi = xb[row * NN + n];
        const float4* wr = sW4 + d * 16;
#pragma unroll
        for (int c4 = 0; c4 < 16; c4++) {
            float4 w = wr[c4];
            acc[4 * c4 + 0] += xi * w.x;
            acc[4 * c4 + 1] += xi * w.y;
            acc[4 * c4 + 2] += xi * w.z;
            acc[4 * c4 + 3] += xi * w.w;
        }
    }

    size_t off = ((size_t)b * NN + n) * 64;
    float4* lo = (float4*)(out + off);
#pragma unroll
    for (int k = 0; k < 16; k++)
        lo[k] = make_float4(acc[4 * k], acc[4 * k + 1], acc[4 * k + 2], acc[4 * k + 3]);

    if (write_pred) {
        float m = acc[0];
#pragma unroll
        for (int c = 1; c < 64; c++) m = fmaxf(m, acc[c]);
        float sum = 0.f;
#pragma unroll
        for (int c = 0; c < 64; c++) { acc[c] = expf(acc[c] - m); sum += acc[c]; }
        float inv = 1.f / sum;
        float4* pr = (float4*)(out + (size_t)BB * NN * 64 + off);
#pragma unroll
        for (int k = 0; k < 16; k++)
            pr[k] = make_float4(acc[4 * k] * inv, acc[4 * k + 1] * inv,
                                acc[4 * k + 2] * inv, acc[4 * k + 3] * inv);
    }
}

extern "C" void kernel_launch(void* const* d_in, const int* in_sizes, int n_in,
                              void* d_out, int out_size) {
    const float* x     = (const float*)d_in[0];  // (16,160,2048)
    const float* alpha = (const float*)d_in[1];  // (3,64)
    const float* kp    = (const float*)d_in[2];  // (1,)
    const float* emb   = (const float*)d_in[3];  // (64,64)
    const float* Mm    = (const float*)d_in[4];  // (64,64)
    float* out = (float*)d_out;

    int write_pred = (out_size >= 2 * BB * NN * 64) ? 1 : 0;

    k1_corr<<<dim3(NCH, BB), 256>>>(x);
    k2_solve<<<BB, 256>>>(alpha, kp, emb, Mm);
    k3_out<<<dim3(NN / 128, BB), 128>>>(x, out, write_pred);
}

// round 5
// speedup vs baseline: 1.1589x; 1.1589x over previous
#include <cuda_runtime.h>
#include <math.h>

#define BB 16
#define NN 2048
#define DIN 160
#define NCTX 2047
#define NCH 64
#define CHUNK 32

// scratch (no allocations allowed)
__device__ float g_part[NCH * BB * 96 * 32];  // per-chunk partial correlations
__device__ float g_sum[BB * 96 * 32];         // reduced correlations per batch
__device__ float g_W[BB * 96 * 64];           // per-batch combined weight [V(32x64); Emb(64x64)]

// ---------------------------------------------------------------------------
// Kernel 1: per (chunk,batch) partial of res[r][j] = sum_{n in chunk,n<2047} x[b,r,n]*x[b,j,n]
//           r in [0,96), j in [0,32). One 96x32 tile per block, 1024 blocks.
// ---------------------------------------------------------------------------
__global__ void __launch_bounds__(256) k1_corr(const float* __restrict__ x) {
    int b = blockIdx.y, ch = blockIdx.x, tid = threadIdx.x;
    __shared__ float sh[96 * 33];
    float acc[12];
#pragma unroll
    for (int k = 0; k < 12; k++) acc[k] = 0.f;

    int cg = tid & 15;   // col group: cols 2*cg, 2*cg+1
    int rg = tid >> 4;   // row group: rows 6*rg .. 6*rg+5
    const float* xb = x + (size_t)b * DIN * NN;
    int n0 = ch * CHUNK;

    // cooperative load of tile [96 rows][32 cols]
#pragma unroll
    for (int k = 0; k < 12; k++) {
        int idx = tid + k * 256;
        int r = idx >> 5, c = idx & 31;
        int n = n0 + c;
        sh[r * 33 + c] = (n < NCTX) ? xb[r * NN + n] : 0.f;
    }
    __syncthreads();

#pragma unroll
    for (int nn = 0; nn < 32; nn++) {
        float q0 = sh[(2 * cg) * 33 + nn];
        float q1 = sh[(2 * cg + 1) * 33 + nn];
#pragma unroll
        for (int k = 0; k < 6; k++) {
            float v = sh[(6 * rg + k) * 33 + nn];
            acc[2 * k]     += v * q0;
            acc[2 * k + 1] += v * q1;
        }
    }

    float* out = g_part + (size_t)(ch * BB + b) * 3072;
#pragma unroll
    for (int k = 0; k < 6; k++) {
        out[(6 * rg + k) * 32 + 2 * cg]     = acc[2 * k];
        out[(6 * rg + k) * 32 + 2 * cg + 1] = acc[2 * k + 1];
    }
}

// ---------------------------------------------------------------------------
// Kernel 1b: reduce partials over 64 chunks. grid (12, 16), 256 thr; 1 elem/thread.
// ---------------------------------------------------------------------------
__global__ void __launch_bounds__(256) k1_reduce() {
    int b = blockIdx.y;
    int e = blockIdx.x * 256 + threadIdx.x;   // 0..3071
    float s = 0.f;
#pragma unroll 16
    for (int ch = 0; ch < NCH; ch++)
        s += g_part[(size_t)(ch * BB + b) * 3072 + e];
    g_sum[(size_t)b * 3072 + e] = s;
}

// ---------------------------------------------------------------------------
// Kernel 2: per-batch small algebra (one block per batch).
//   P(32x32), U(64x32) from g_sum; S0 = Emb*U;
//   loop l: R += c*diag(a_l)*S ; Tmp = c*diag(a_l)*S*P ; S += M*Tmp
//   V = R^T * Emb (32x64); g_W[b] = [V ; Emb]
// ---------------------------------------------------------------------------
__global__ void __launch_bounds__(256) k2_solve(const float* __restrict__ alpha,
                         const float* __restrict__ kparam,
                         const float* __restrict__ emb,
                         const float* __restrict__ Mm) {
    int b = blockIdx.x, tid = threadIdx.x;
    __shared__ float smem[11264];
    float* sEM = smem;           // 4096: Emb, later M, later Emb again
    float* sP  = smem + 4096;    // 1024
    float* sS  = smem + 5120;    // 2048
    float* sT  = smem + 7168;    // 2048: U, later Tmp
    float* sR  = smem + 9216;    // 2048

    float cfac = kparam[0] / (float)NCTX;

    for (int e = tid; e < 1024; e += 256) sP[e] = g_sum[(size_t)b * 3072 + e];
    for (int e = tid; e < 2048; e += 256) sT[e] = g_sum[(size_t)b * 3072 + 1024 + e];
    for (int e = tid; e < 4096; e += 256) sEM[e] = emb[e];
    __syncthreads();

    // S0 = Emb * U   (64x64 * 64x32)
#pragma unroll
    for (int k = 0; k < 8; k++) {
        int e = tid + k * 256;
        int i = e >> 5, j = e & 31;
        float s = 0.f;
#pragma unroll 8
        for (int c = 0; c < 64; c++) s += sEM[i * 64 + c] * sT[c * 32 + j];
        sS[e] = s;
    }
    __syncthreads();

    // M into sEM, zero R
    for (int e = tid; e < 4096; e += 256) sEM[e] = Mm[e];
    for (int e = tid; e < 2048; e += 256) sR[e] = 0.f;
    __syncthreads();

    for (int l = 0; l < 3; l++) {
        // phase A: R += c*a_i*S ; Tmp = c*a_i * (S*P)
#pragma unroll
        for (int k = 0; k < 8; k++) {
            int e = tid + k * 256;
            int i = e >> 5, j = e & 31;
            float a = cfac * alpha[l * 64 + i];
            sR[e] += a * sS[e];
            float t = 0.f;
#pragma unroll 8
            for (int jj = 0; jj < 32; jj++) t += sS[i * 32 + jj] * sP[jj * 32 + j];
            sT[e] = a * t;
        }
        __syncthreads();
        // phase B: S += M * Tmp
#pragma unroll
        for (int k = 0; k < 8; k++) {
            int e = tid + k * 256;
            int r = e >> 5, j = e & 31;
            float t = 0.f;
#pragma unroll 8
            for (int i = 0; i < 64; i++) t += sEM[r * 64 + i] * sT[i * 32 + j];
            sS[e] += t;
        }
        __syncthreads();
    }

    // reload Emb
    for (int e = tid; e < 4096; e += 256) sEM[e] = emb[e];
    __syncthreads();

    // V[j][c] = sum_i R[i][j] * Emb[i][c]   (rows 0:32 of g_W[b])
#pragma unroll
    for (int k = 0; k < 8; k++) {
        int e = tid + k * 256;
        int j = e >> 6, c = e & 63;
        float v = 0.f;
#pragma unroll 8
        for (int i = 0; i < 64; i++) v += sR[i * 32 + j] * sEM[i * 64 + c];
        g_W[(size_t)(b * 96 + j) * 64 + c] = v;
    }
    // rows 32:96 of g_W[b] = Emb
    for (int e = tid; e < 4096; e += 256)
        g_W[(size_t)b * 96 * 64 + 32 * 64 + e] = sEM[e];
}

// ---------------------------------------------------------------------------
// Kernel 3: logits + softmax, packed f32x2 FMA (FFMA2).
//   logits[b,n,c] = sum_{d<32} x[b,d,n]*W[d][c] + sum_{d<64} x[b,96+d,n]*W[32+d][c]
// ---------------------------------------------------------------------------
__device__ __forceinline__ unsigned long long splat2(float v) {
    unsigned long long r;
    asm("mov.b64 %0, {%1, %1};" : "=l"(r) : "f"(v));
    return r;
}
__device__ __forceinline__ unsigned long long pack2(float a, float b) {
    unsigned long long r;
    asm("mov.b64 %0, {%1, %2};" : "=l"(r) : "f"(a), "f"(b));
    return r;
}
__device__ __forceinline__ void fma2(unsigned long long& acc,
                                     unsigned long long a, unsigned long long b) {
    asm("fma.rn.f32x2 %0, %1, %2, %0;" : "+l"(acc) : "l"(a), "l"(b));
}
__device__ __forceinline__ void unpack2(unsigned long long p, float& a, float& b) {
    asm("mov.b64 {%0, %1}, %2;" : "=f"(a), "=f"(b) : "l"(p));
}

__global__ void __launch_bounds__(128) k3_out(const float* __restrict__ x,
                                              float* __restrict__ out,
                                              int write_pred) {
    int b = blockIdx.y;
    int n = blockIdx.x * 128 + threadIdx.x;
    __shared__ float sW[96 * 64];
    {
        const float4* src = (const float4*)(g_W + (size_t)b * 6144);
        float4* dst = (float4*)sW;
        for (int e = threadIdx.x; e < 1536; e += 128) dst[e] = src[e];
    }
    __syncthreads();

    const float* xb = x + (size_t)b * DIN * NN;

    unsigned long long acc[32];
#pragma unroll
    for (int c = 0; c < 32; c++) acc[c] = 0ull;

    // rows 0..31 of x
#pragma unroll 8
    for (int d = 0; d < 32; d++) {
        float xi = xb[d * NN + n];
        unsigned long long xi2 = splat2(xi);
        const float4* wr = (const float4*)(sW + d * 64);
#pragma unroll
        for (int j = 0; j < 16; j++) {
            float4 w = wr[j];
            fma2(acc[2 * j],     xi2, pack2(w.x, w.y));
            fma2(acc[2 * j + 1], xi2, pack2(w.z, w.w));
        }
    }
    // rows 96..159 of x vs W rows 32..95
#pragma unroll 8
    for (int d = 0; d < 64; d++) {
        float xi = xb[(96 + d) * NN + n];
        unsigned long long xi2 = splat2(xi);
        const float4* wr = (const float4*)(sW + (32 + d) * 64);
#pragma unroll
        for (int j = 0; j < 16; j++) {
            float4 w = wr[j];
            fma2(acc[2 * j],     xi2, pack2(w.x, w.y));
            fma2(acc[2 * j + 1], xi2, pack2(w.z, w.w));
        }
    }

    float v[64];
#pragma unroll
    for (int c = 0; c < 32; c++) unpack2(acc[c], v[2 * c], v[2 * c + 1]);

    size_t off = ((size_t)b * NN + n) * 64;
    float4* lo = (float4*)(out + off);
#pragma unroll
    for (int k = 0; k < 16; k++)
        lo[k] = make_float4(v[4 * k], v[4 * k + 1], v[4 * k + 2], v[4 * k + 3]);

    if (write_pred) {
        float m = v[0];
#pragma unroll
        for (int c = 1; c < 64; c++) m = fmaxf(m, v[c]);
        float sum = 0.f;
#pragma unroll
        for (int c = 0; c < 64; c++) { v[c] = __expf(v[c] - m); sum += v[c]; }
        float inv = 1.f / sum;
        float4* pr = (float4*)(out + (size_t)BB * NN * 64 + off);
#pragma unroll
        for (int k = 0; k < 16; k++)
            pr[k] = make_float4(v[4 * k] * inv, v[4 * k + 1] * inv,
                                v[4 * k + 2] * inv, v[4 * k + 3] * inv);
    }
}

extern "C" void kernel_launch(void* const* d_in, const int* in_sizes, int n_in,
                              void* d_out, int out_size) {
    const float* x     = (const float*)d_in[0];  // (16,160,2048)
    const float* alpha = (const float*)d_in[1];  // (3,64)
    const float* kp    = (const float*)d_in[2];  // (1,)
    const float* emb   = (const float*)d_in[3];  // (64,64)
    const float* Mm    = (const float*)d_in[4];  // (64,64)
    float* out = (float*)d_out;

    int write_pred = (out_size >= 2 * BB * NN * 64) ? 1 : 0;

    k1_corr<<<dim3(NCH, BB), 256>>>(x);
    k1_reduce<<<dim3(12, BB), 256>>>();
    k2_solve<<<BB, 256>>>(alpha, kp, emb, Mm);
    k3_out<<<dim3(NN / 128, BB), 128>>>(x, out, write_pred);
}